// round 15
// baseline (speedup 1.0000x reference)
#include <cuda_runtime.h>
#include <cuda_bf16.h>
#include <cuda_fp16.h>
#include <math.h>
#include <stdint.h>

#define B_   8
#define C1   128
#define C2   256
#define H_   80
#define W_   80
#define P_   6400
#define NPT  5

#define TPIX   64           // gemm CTA pixel tile
#define NCHUNK 10
#define OPITCH 66           // fp32 elements

// ---------------- device scratch ----------------
__device__ int2   g_id2[B_ * NPT * P_];
__device__ float4 g_gw [B_ * NPT * P_];
__device__ uint4  g_wfrag[NCHUNK * 4 * 4 * 4 * 32];        // B fragments (327 KB)
__device__ uint2  g_x4[(size_t)B_ * 64 * P_];              // quad mirror (26 MB)
__device__ uint4  g_afrag[(size_t)B_ * NCHUNK * 400 * 4 * 32];  // A fragments (65 MB)
__device__ float  g_pwT[C1 * 9 * 12];

__device__ __forceinline__ uint32_t smem_u32(const void* p) {
    uint32_t a;
    asm("{ .reg .u64 t; cvta.to.shared.u64 t, %1; cvt.u32.u64 %0, t; }" : "=r"(a) : "l"(p));
    return a;
}

// r = {lo = f16(a), hi = f16(b)}
#define CVT2H(r, a, b) asm("cvt.rn.f16x2.f32 %0, %1, %2;" : "=r"(r) : "f"(b), "f"(a))

__device__ __forceinline__ float2 up2(uint32_t u) {
    return __half22float2(*(const __half2*)&u);
}

__device__ __forceinline__ void mma16816(float* d, const uint32_t* a, const uint32_t* b) {
    asm volatile("mma.sync.aligned.m16n8k16.row.col.f32.f16.f16.f32 "
        "{%0,%1,%2,%3}, {%4,%5,%6,%7}, {%8,%9}, {%0,%1,%2,%3};"
        : "+f"(d[0]), "+f"(d[1]), "+f"(d[2]), "+f"(d[3])
        : "r"(a[0]), "r"(a[1]), "r"(a[2]), "r"(a[3]), "r"(b[0]), "r"(b[1]));
}

#define SM_BN    0
#define SM_ST    2048
#define SM_TOTAL (SM_ST + 128 * OPITCH * 4)    // 35840

// ---------------------------------------------------------------------------
// prep: B fragments per m16n8k16 spec + offset-weight transpose
// ---------------------------------------------------------------------------
__global__ void prep_kernel(const float* __restrict__ cw, const float* __restrict__ pw) {
    int e = blockIdx.x * 256 + threadIdx.x;
    if (e < NCHUNK * 2048) {
        int lid = e & 31;
        int g   = (e >> 5) & 3;
        int ks  = (e >> 7) & 3;
        int wn  = (e >> 9) & 3;
        int c   = e >> 11;
        int kpt = c >> 1;
        int c1b = (c & 1) * 64;
        int k0  = ks * 16 + (lid & 3) * 2;
        unsigned r[4];
#pragma unroll
        for (int j = 0; j < 2; j++) {
            int c2 = wn * 64 + (g * 2 + j) * 8 + (lid >> 2);
            const float* wrow = cw + (size_t)c2 * C1 * NPT + kpt;
            float v0 = wrow[(c1b + k0) * NPT];
            float v1 = wrow[(c1b + k0 + 1) * NPT];
            float v8 = wrow[(c1b + k0 + 8) * NPT];
            float v9 = wrow[(c1b + k0 + 9) * NPT];
            CVT2H(r[2 * j],     v0, v1);
            CVT2H(r[2 * j + 1], v8, v9);
        }
        g_wfrag[e] = make_uint4(r[0], r[1], r[2], r[3]);
    }
    if (e < C1 * 9 * 12) {
        int j  = e % 12;
        int ct = e / 12;
        int c  = ct / 9;
        int tt = ct % 9;
        g_pwT[e] = (j < 10) ? pw[(j * C1 + c) * 9 + tt] : 0.f;
    }
}

// ---------------------------------------------------------------------------
// offset conv + bilinear params (clamp folded) + quad mirror  (same as R14)
// ---------------------------------------------------------------------------
__global__ __launch_bounds__(256)
void offset_kernel(const float* __restrict__ x, const float* __restrict__ pb) {
    extern __shared__ float sw[];
    int t = threadIdx.x;
    for (int i = t; i < C1 * 9 * 12; i += 256) sw[i] = g_pwT[i];
    __syncthreads();

    int tid = blockIdx.x * 256 + t;
    int b = tid / P_, p = tid % P_, h = p / W_, w = p % W_;

    float acc[10];
#pragma unroll
    for (int j = 0; j < 10; j++) acc[j] = pb[j];

    int off[9]; bool ok[9];
#pragma unroll
    for (int tt = 0; tt < 9; tt++) {
        int dh = tt / 3 - 1, dw = tt % 3 - 1;
        int hh = h + dh, ww = w + dw;
        ok[tt]  = (hh >= 0) && (hh < H_) && (ww >= 0) && (ww < W_);
        off[tt] = hh * W_ + ww;
    }

    const float* xb = x + (size_t)b * C1 * P_;
    uint2* x4b = g_x4 + (size_t)b * 64 * P_ + p;
    float pv4 = 0.f, pv5 = 0.f;
    for (int c = 0; c < C1; c++) {
        const float* xc = xb + c * P_;
        float v[9];
#pragma unroll
        for (int tt = 0; tt < 9; tt++) v[tt] = ok[tt] ? __ldg(xc + off[tt]) : 0.f;
        if (c & 1) {
            unsigned lo, hi;
            CVT2H(lo, pv4, v[4]);
            CVT2H(hi, pv5, v[5]);
            x4b[(size_t)(c >> 1) * P_] = make_uint2(lo, hi);
        }
        pv4 = v[4]; pv5 = v[5];
        const float* wc = sw + c * 108;
#pragma unroll
        for (int tt = 0; tt < 9; tt++) {
            float4 w0 = *(const float4*)(wc + tt * 12);
            float4 w1 = *(const float4*)(wc + tt * 12 + 4);
            float2 w2 = *(const float2*)(wc + tt * 12 + 8);
            float xv = v[tt];
            acc[0] = fmaf(xv, w0.x, acc[0]); acc[1] = fmaf(xv, w0.y, acc[1]);
            acc[2] = fmaf(xv, w0.z, acc[2]); acc[3] = fmaf(xv, w0.w, acc[3]);
            acc[4] = fmaf(xv, w1.x, acc[4]); acc[5] = fmaf(xv, w1.y, acc[5]);
            acc[6] = fmaf(xv, w1.z, acc[6]); acc[7] = fmaf(xv, w1.w, acc[7]);
            acc[8] = fmaf(xv, w2.x, acc[8]); acc[9] = fmaf(xv, w2.y, acc[9]);
        }
    }

    const float pnx[NPT] = {0.f, 0.f, 1.f, 1.f, 2.f};
    const float pny[NPT] = {0.f, 1.f, 0.f, 1.f, 0.f};

#pragma unroll
    for (int k = 0; k < NPT; k++) {
        float px = acc[k]       + (float)h + pnx[k];
        float py = acc[NPT + k] + (float)w + pny[k];
        float pf = floorf(px), qf = floorf(py);
        float xl = fminf(fmaxf(pf,       0.f), (float)(H_ - 1));
        float yl = fminf(fmaxf(qf,       0.f), (float)(W_ - 1));
        float xr = fminf(fmaxf(pf + 1.f, 0.f), (float)(H_ - 1));
        float yr = fminf(fmaxf(qf + 1.f, 0.f), (float)(W_ - 1));
        float pxc = fminf(fmaxf(px, 0.f), (float)(H_ - 1));
        float pyc = fminf(fmaxf(py, 0.f), (float)(W_ - 1));
        float ax = 1.f + xl - pxc;
        float bx = 1.f - xr + pxc;
        float ay = 1.f + yl - pyc;
        float by = 1.f - yr + pyc;
        int ixl = (int)xl, iyl = (int)yl, ixr = (int)xr, iyr = (int)yr;
        float rx0, rx1, cy0, cy1;
        if (ixl == ixr) { rx0 = ax + bx; rx1 = 0.f; } else { rx0 = ax; rx1 = bx; }
        if (iyl == iyr) { cy0 = ay + by; cy1 = 0.f; } else { cy0 = ay; cy1 = by; }
        int gi = (b * NPT + k) * P_ + p;
        g_id2[gi] = make_int2(ixl * W_ + iyl, ixr * W_ + iyl);
        g_gw[gi]  = make_float4(rx0 * cy0, rx0 * cy1, rx1 * cy0, rx1 * cy1);
    }
}

// ---------------------------------------------------------------------------
// gather: writes A in mma fragment layout. Warp = one (g16, 2 ks) tile.
// No smem, no barriers. Grid (100, 10, 8) x 256.
// ---------------------------------------------------------------------------
__device__ __forceinline__ unsigned samp(const uint2* x4c, size_t qoff,
                                         int2 id, float4 gw) {
    const uint2* xq = x4c + qoff;
    uint2 q0 = __ldg(xq + id.x);
    uint2 q1 = __ldg(xq + id.y);
    float2 r00 = up2(q0.x), r01 = up2(q0.y);
    float2 r10 = up2(q1.x), r11 = up2(q1.y);
    float ve = gw.x * r00.x + gw.y * r01.x + gw.z * r10.x + gw.w * r11.x;
    float vo = gw.x * r00.y + gw.y * r01.y + gw.z * r10.y + gw.w * r11.y;
    unsigned h; CVT2H(h, ve, vo);
    return h;
}

__global__ __launch_bounds__(256)
void gather_kernel() {
    int t = threadIdx.x, wid = t >> 5, lid = t & 31;
    int b = blockIdx.z, c = blockIdx.y;
    int g16 = blockIdx.x * 4 + (wid & 3);
    int ks2 = wid >> 2;
    int kpt = c >> 1;

    int p_a = g16 * 16 + (lid >> 2);
    int gia = (b * NPT + kpt) * P_ + p_a;
    int2   ida = __ldg(&g_id2[gia]);
    int2   idb = __ldg(&g_id2[gia + 8]);
    float4 gwa = __ldg(&g_gw[gia]);
    float4 gwb = __ldg(&g_gw[gia + 8]);

    const uint2* x4c = g_x4 + (size_t)b * 64 * P_ + (size_t)(c & 1) * 32 * P_;
    uint4* dst = g_afrag + ((size_t)(b * NCHUNK + c) * 400 + g16) * 128 + lid;

#pragma unroll
    for (int kk = 0; kk < 2; kk++) {
        int ks = ks2 * 2 + kk;
        int qa = ks * 8 + (lid & 3);
        size_t qo0 = (size_t)qa * P_;
        size_t qo1 = (size_t)(qa + 4) * P_;
        unsigned a0 = samp(x4c, qo0, ida, gwa);
        unsigned a1 = samp(x4c, qo0, idb, gwb);
        unsigned a2 = samp(x4c, qo1, ida, gwa);
        unsigned a3 = samp(x4c, qo1, idb, gwb);
        dst[ks * 32] = make_uint4(a0, a1, a2, a3);
    }
}

// ---------------------------------------------------------------------------
// gemm: fragment-direct. 256 threads, 64 pixels x 256 c2, no smem main loop.
// ---------------------------------------------------------------------------
#define LOADSTEP(s_, buf_) do {                                               \
    int c_ = (s_) >> 2, ks_ = (s_) & 3;                                       \
    const uint4* pa_ = Abase + c_ * 51200 + ks_ * 32;                         \
    af[buf_][0] = __ldg(pa_);                                                 \
    af[buf_][1] = __ldg(pa_ + 128);                                           \
    const uint4* pb_ = Bbase + c_ * 2048 + ks_ * 128;                         \
    bf[buf_][0] = __ldg(pb_);                                                 \
    bf[buf_][1] = __ldg(pb_ + 32);                                            \
    bf[buf_][2] = __ldg(pb_ + 64);                                            \
    bf[buf_][3] = __ldg(pb_ + 96);                                            \
} while (0)

#define MMASTEP(buf_) do {                                                    \
    _Pragma("unroll")                                                         \
    for (int g = 0; g < 4; g++)                                               \
        _Pragma("unroll")                                                     \
        for (int mt = 0; mt < 2; mt++) {                                      \
            mma16816(acc[mt][2 * g], (const uint32_t*)&af[buf_][mt],          \
                     (const uint32_t*)&bf[buf_][g]);                          \
            mma16816(acc[mt][2 * g + 1], (const uint32_t*)&af[buf_][mt],      \
                     (const uint32_t*)&bf[buf_][g] + 2);                      \
        }                                                                     \
} while (0)

__global__ __launch_bounds__(256, 2)
void gemm_kernel(const float* __restrict__ bng, const float* __restrict__ bnb,
                 const float* __restrict__ bnm, const float* __restrict__ bnv,
                 float* __restrict__ out) {
    extern __shared__ char smem[];
    int t = threadIdx.x, wid = t >> 5, lid = t & 31;
    int b = blockIdx.y;
    int p0 = blockIdx.x * TPIX;

    {
        float sc = bng[t] * rsqrtf(bnv[t] + 1e-5f);
        ((float*)(smem + SM_BN))[t]       = sc;
        ((float*)(smem + SM_BN))[256 + t] = bnb[t] - bnm[t] * sc;
    }

    int wm = wid & 1;
    int wn = wid >> 1;
    const uint4* Abase = g_afrag + ((size_t)b * NCHUNK * 400 + (p0 >> 4) + wm * 2) * 128 + lid;
    const uint4* Bbase = g_wfrag + wn * 512 + lid;

    float acc[2][8][4];
#pragma unroll
    for (int mt = 0; mt < 2; mt++)
#pragma unroll
        for (int nt = 0; nt < 8; nt++)
#pragma unroll
            for (int j = 0; j < 4; j++) acc[mt][nt][j] = 0.f;

    uint4 af[2][2], bf[2][4];
    LOADSTEP(0, 0);
#pragma unroll 1
    for (int sp = 0; sp < 20; sp++) {
        int s1 = 2 * sp + 1;
        LOADSTEP(s1, 1);
        MMASTEP(0);
        if (s1 < 39) LOADSTEP(s1 + 1, 0);
        MMASTEP(1);
    }

    __syncthreads();

    // ---- epilogue: BN + SiLU via SMEM transpose ----
    const float* scs = (const float*)(smem + SM_BN);
    const float* shs = scs + 256;
    float* sO = (float*)(smem + SM_ST);
#pragma unroll
    for (int half = 0; half < 2; half++) {
        if ((wn >> 1) == half) {
#pragma unroll
            for (int mt = 0; mt < 2; mt++)
#pragma unroll
                for (int nt = 0; nt < 8; nt++)
#pragma unroll
                    for (int j = 0; j < 4; j++) {
                        int row = wm * 32 + mt * 16 + (lid >> 2) + 8 * (j >> 1);
                        int col = (wn & 1) * 64 + nt * 8 + 2 * (lid & 3) + (j & 1);
                        sO[col * OPITCH + row] = acc[mt][nt][j];
                    }
        }
        __syncthreads();
#pragma unroll
        for (int it = 0; it < 32; it++) {
            int idx = it * 256 + t;
            int c2l = idx >> 6, pp = idx & 63;
            int c2 = half * 128 + c2l;
            float v = sO[c2l * OPITCH + pp] * scs[c2] + shs[c2];
            out[((size_t)b * C2 + c2) * P_ + p0 + pp] = v / (1.f + __expf(-v));
        }
        __syncthreads();
    }
}

// ---------------------------------------------------------------------------
extern "C" void kernel_launch(void* const* d_in, const int* in_sizes, int n_in,
                              void* d_out, int out_size) {
    const float* x   = (const float*)d_in[0];
    const float* pw  = (const float*)d_in[1];
    const float* pb  = (const float*)d_in[2];
    const float* cw  = (const float*)d_in[3];
    const float* bng = (const float*)d_in[4];
    const float* bnb = (const float*)d_in[5];
    const float* bnm = (const float*)d_in[6];
    const float* bnv = (const float*)d_in[7];
    float* out = (float*)d_out;

    cudaFuncSetAttribute(offset_kernel, cudaFuncAttributeMaxDynamicSharedMemorySize, 55296);
    cudaFuncSetAttribute(gemm_kernel,   cudaFuncAttributeMaxDynamicSharedMemorySize, SM_TOTAL);

    prep_kernel<<<80, 256>>>(cw, pw);
    offset_kernel<<<B_ * P_ / 256, 256, 55296>>>(x, pb);
    dim3 gg(100, NCHUNK, B_);
    gather_kernel<<<gg, 256>>>();
    dim3 g2(P_ / TPIX, B_);
    gemm_kernel<<<g2, 256, SM_TOTAL>>>(bng, bnb, bnm, bnv, out);
}

// round 16
// speedup vs baseline: 1.1127x; 1.1127x over previous
#include <cuda_runtime.h>
#include <cuda_bf16.h>
#include <cuda_fp16.h>
#include <math.h>
#include <stdint.h>

#define B_   8
#define C1   128
#define C2   256
#define H_   80
#define W_   80
#define P_   6400
#define NPT  5

#define TPIX   64           // gemm CTA pixel tile
#define NCHUNK 10
#define OPITCH 66           // fp32 elements

// ---------------- device scratch ----------------
__device__ int2   g_id2[B_ * NPT * P_];
__device__ float4 g_gw [B_ * NPT * P_];
__device__ uint4  g_wfrag[NCHUNK * 4 * 4 * 4 * 32];        // B fragments (327 KB)
__device__ uint2  g_x4[(size_t)B_ * 64 * P_];              // quad mirror (26 MB)
__device__ uint4  g_afrag[(size_t)B_ * NCHUNK * 400 * 4 * 32];  // A fragments (65 MB)
__device__ float  g_pwT[C1 * 9 * 12];

__device__ __forceinline__ uint32_t smem_u32(const void* p) {
    uint32_t a;
    asm("{ .reg .u64 t; cvta.to.shared.u64 t, %1; cvt.u32.u64 %0, t; }" : "=r"(a) : "l"(p));
    return a;
}

// r = {lo = f16(a), hi = f16(b)}
#define CVT2H(r, a, b) asm("cvt.rn.f16x2.f32 %0, %1, %2;" : "=r"(r) : "f"(b), "f"(a))

__device__ __forceinline__ float2 up2(uint32_t u) {
    return __half22float2(*(const __half2*)&u);
}

__device__ __forceinline__ void mma16816(float* d, const uint32_t* a, const uint32_t* b) {
    asm volatile("mma.sync.aligned.m16n8k16.row.col.f32.f16.f16.f32 "
        "{%0,%1,%2,%3}, {%4,%5,%6,%7}, {%8,%9}, {%0,%1,%2,%3};"
        : "+f"(d[0]), "+f"(d[1]), "+f"(d[2]), "+f"(d[3])
        : "r"(a[0]), "r"(a[1]), "r"(a[2]), "r"(a[3]), "r"(b[0]), "r"(b[1]));
}

#define SM_BN    0
#define SM_ST    2048
#define SM_TOTAL (SM_ST + 128 * OPITCH * 4)    // 35840

// ---------------------------------------------------------------------------
// prep: B fragments per m16n8k16 spec + offset-weight transpose
// ---------------------------------------------------------------------------
__global__ void prep_kernel(const float* __restrict__ cw, const float* __restrict__ pw) {
    int e = blockIdx.x * 256 + threadIdx.x;
    if (e < NCHUNK * 2048) {
        int lid = e & 31;
        int g   = (e >> 5) & 3;
        int ks  = (e >> 7) & 3;
        int wn  = (e >> 9) & 3;
        int c   = e >> 11;
        int kpt = c >> 1;
        int c1b = (c & 1) * 64;
        int k0  = ks * 16 + (lid & 3) * 2;
        unsigned r[4];
#pragma unroll
        for (int j = 0; j < 2; j++) {
            int c2 = wn * 64 + (g * 2 + j) * 8 + (lid >> 2);
            const float* wrow = cw + (size_t)c2 * C1 * NPT + kpt;
            float v0 = wrow[(c1b + k0) * NPT];
            float v1 = wrow[(c1b + k0 + 1) * NPT];
            float v8 = wrow[(c1b + k0 + 8) * NPT];
            float v9 = wrow[(c1b + k0 + 9) * NPT];
            CVT2H(r[2 * j],     v0, v1);
            CVT2H(r[2 * j + 1], v8, v9);
        }
        g_wfrag[e] = make_uint4(r[0], r[1], r[2], r[3]);
    }
    if (e < C1 * 9 * 12) {
        int j  = e % 12;
        int ct = e / 12;
        int c  = ct / 9;
        int tt = ct % 9;
        g_pwT[e] = (j < 10) ? pw[(j * C1 + c) * 9 + tt] : 0.f;
    }
}

// ---------------------------------------------------------------------------
// offset conv + bilinear params (clamp folded) + quad mirror
// ---------------------------------------------------------------------------
__global__ __launch_bounds__(256)
void offset_kernel(const float* __restrict__ x, const float* __restrict__ pb) {
    extern __shared__ float sw[];
    int t = threadIdx.x;
    for (int i = t; i < C1 * 9 * 12; i += 256) sw[i] = g_pwT[i];
    __syncthreads();

    int tid = blockIdx.x * 256 + t;
    int b = tid / P_, p = tid % P_, h = p / W_, w = p % W_;

    float acc[10];
#pragma unroll
    for (int j = 0; j < 10; j++) acc[j] = pb[j];

    int off[9]; bool ok[9];
#pragma unroll
    for (int tt = 0; tt < 9; tt++) {
        int dh = tt / 3 - 1, dw = tt % 3 - 1;
        int hh = h + dh, ww = w + dw;
        ok[tt]  = (hh >= 0) && (hh < H_) && (ww >= 0) && (ww < W_);
        off[tt] = hh * W_ + ww;
    }

    const float* xb = x + (size_t)b * C1 * P_;
    uint2* x4b = g_x4 + (size_t)b * 64 * P_ + p;
    float pv4 = 0.f, pv5 = 0.f;
    for (int c = 0; c < C1; c++) {
        const float* xc = xb + c * P_;
        float v[9];
#pragma unroll
        for (int tt = 0; tt < 9; tt++) v[tt] = ok[tt] ? __ldg(xc + off[tt]) : 0.f;
        if (c & 1) {
            unsigned lo, hi;
            CVT2H(lo, pv4, v[4]);
            CVT2H(hi, pv5, v[5]);
            x4b[(size_t)(c >> 1) * P_] = make_uint2(lo, hi);
        }
        pv4 = v[4]; pv5 = v[5];
        const float* wc = sw + c * 108;
#pragma unroll
        for (int tt = 0; tt < 9; tt++) {
            float4 w0 = *(const float4*)(wc + tt * 12);
            float4 w1 = *(const float4*)(wc + tt * 12 + 4);
            float2 w2 = *(const float2*)(wc + tt * 12 + 8);
            float xv = v[tt];
            acc[0] = fmaf(xv, w0.x, acc[0]); acc[1] = fmaf(xv, w0.y, acc[1]);
            acc[2] = fmaf(xv, w0.z, acc[2]); acc[3] = fmaf(xv, w0.w, acc[3]);
            acc[4] = fmaf(xv, w1.x, acc[4]); acc[5] = fmaf(xv, w1.y, acc[5]);
            acc[6] = fmaf(xv, w1.z, acc[6]); acc[7] = fmaf(xv, w1.w, acc[7]);
            acc[8] = fmaf(xv, w2.x, acc[8]); acc[9] = fmaf(xv, w2.y, acc[9]);
        }
    }

    const float pnx[NPT] = {0.f, 0.f, 1.f, 1.f, 2.f};
    const float pny[NPT] = {0.f, 1.f, 0.f, 1.f, 0.f};

#pragma unroll
    for (int k = 0; k < NPT; k++) {
        float px = acc[k]       + (float)h + pnx[k];
        float py = acc[NPT + k] + (float)w + pny[k];
        float pf = floorf(px), qf = floorf(py);
        float xl = fminf(fmaxf(pf,       0.f), (float)(H_ - 1));
        float yl = fminf(fmaxf(qf,       0.f), (float)(W_ - 1));
        float xr = fminf(fmaxf(pf + 1.f, 0.f), (float)(H_ - 1));
        float yr = fminf(fmaxf(qf + 1.f, 0.f), (float)(W_ - 1));
        float pxc = fminf(fmaxf(px, 0.f), (float)(H_ - 1));
        float pyc = fminf(fmaxf(py, 0.f), (float)(W_ - 1));
        float ax = 1.f + xl - pxc;
        float bx = 1.f - xr + pxc;
        float ay = 1.f + yl - pyc;
        float by = 1.f - yr + pyc;
        int ixl = (int)xl, iyl = (int)yl, ixr = (int)xr, iyr = (int)yr;
        float rx0, rx1, cy0, cy1;
        if (ixl == ixr) { rx0 = ax + bx; rx1 = 0.f; } else { rx0 = ax; rx1 = bx; }
        if (iyl == iyr) { cy0 = ay + by; cy1 = 0.f; } else { cy0 = ay; cy1 = by; }
        int gi = (b * NPT + k) * P_ + p;
        g_id2[gi] = make_int2(ixl * W_ + iyl, ixr * W_ + iyl);
        g_gw[gi]  = make_float4(rx0 * cy0, rx0 * cy1, rx1 * cy0, rx1 * cy1);
    }
}

// ---------------------------------------------------------------------------
// gather: lane = pixel (coalesced LDG.64), warp-private smem transpose
// (pitch 36 -> conflict-free both directions), fragment-layout STG.128.
// No CTA barriers. Grid (25, 10, 8) x 256 (8 warps; warp = 32 pixels x 1 chunk).
// ---------------------------------------------------------------------------
__global__ __launch_bounds__(256)
void gather_kernel() {
    __shared__ uint32_t sT[8][32 * 36];     // per-warp 32 quads x pitch 36
    int t = threadIdx.x, wid = t >> 5, lid = t & 31;
    int b = blockIdx.z, c = blockIdx.y;
    int p0 = blockIdx.x * 256 + wid * 32;
    int kpt = c >> 1;
    int pix = p0 + lid;

    int gi = (b * NPT + kpt) * P_ + pix;
    int2   id = __ldg(&g_id2[gi]);
    float4 gw = __ldg(&g_gw[gi]);
    const uint2* x4c = g_x4 + (size_t)b * 64 * P_ + (size_t)(c & 1) * 32 * P_;
    uint32_t* sW = &sT[wid][0];

#pragma unroll 8
    for (int q = 0; q < 32; q++) {
        const uint2* xq = x4c + (size_t)q * P_;
        uint2 q0 = __ldg(xq + id.x);
        uint2 q1 = __ldg(xq + id.y);
        float2 r00 = up2(q0.x), r01 = up2(q0.y);
        float2 r10 = up2(q1.x), r11 = up2(q1.y);
        float ve = gw.x * r00.x + gw.y * r01.x + gw.z * r10.x + gw.w * r11.x;
        float vo = gw.x * r00.y + gw.y * r01.y + gw.z * r10.y + gw.w * r11.y;
        unsigned h; CVT2H(h, ve, vo);
        sW[q * 36 + lid] = h;
    }
    __syncwarp(0xffffffffu);

    // fragment-order readback + coalesced store
    uint4* dstbase = g_afrag + ((size_t)(b * NCHUNK + c) * 400 + (p0 >> 4)) * 128 + lid;
    int prow = lid >> 2;
    int qcol = lid & 3;
#pragma unroll
    for (int m = 0; m < 2; m++) {
#pragma unroll
        for (int ks = 0; ks < 4; ks++) {
            int pr = m * 16 + prow;
            int qc = ks * 8 + qcol;
            uint32_t a0 = sW[qc * 36 + pr];
            uint32_t a1 = sW[qc * 36 + pr + 8];
            uint32_t a2 = sW[(qc + 4) * 36 + pr];
            uint32_t a3 = sW[(qc + 4) * 36 + pr + 8];
            dstbase[m * 128 + ks * 32] = make_uint4(a0, a1, a2, a3);
        }
    }
}

// ---------------------------------------------------------------------------
// gemm: fragment-direct. 256 threads, 64 pixels x 256 c2, no smem main loop.
// ---------------------------------------------------------------------------
#define LOADSTEP(s_, buf_) do {                                               \
    int c_ = (s_) >> 2, ks_ = (s_) & 3;                                       \
    const uint4* pa_ = Abase + c_ * 51200 + ks_ * 32;                         \
    af[buf_][0] = __ldg(pa_);                                                 \
    af[buf_][1] = __ldg(pa_ + 128);                                           \
    const uint4* pb_ = Bbase + c_ * 2048 + ks_ * 128;                         \
    bf[buf_][0] = __ldg(pb_);                                                 \
    bf[buf_][1] = __ldg(pb_ + 32);                                            \
    bf[buf_][2] = __ldg(pb_ + 64);                                            \
    bf[buf_][3] = __ldg(pb_ + 96);                                            \
} while (0)

#define MMASTEP(buf_) do {                                                    \
    _Pragma("unroll")                                                         \
    for (int g = 0; g < 4; g++)                                               \
        _Pragma("unroll")                                                     \
        for (int mt = 0; mt < 2; mt++) {                                      \
            mma16816(acc[mt][2 * g], (const uint32_t*)&af[buf_][mt],          \
                     (const uint32_t*)&bf[buf_][g]);                          \
            mma16816(acc[mt][2 * g + 1], (const uint32_t*)&af[buf_][mt],      \
                     (const uint32_t*)&bf[buf_][g] + 2);                      \
        }                                                                     \
} while (0)

__global__ __launch_bounds__(256, 2)
void gemm_kernel(const float* __restrict__ bng, const float* __restrict__ bnb,
                 const float* __restrict__ bnm, const float* __restrict__ bnv,
                 float* __restrict__ out) {
    extern __shared__ char smem[];
    int t = threadIdx.x, wid = t >> 5, lid = t & 31;
    int b = blockIdx.y;
    int p0 = blockIdx.x * TPIX;

    {
        float sc = bng[t] * rsqrtf(bnv[t] + 1e-5f);
        ((float*)(smem + SM_BN))[t]       = sc;
        ((float*)(smem + SM_BN))[256 + t] = bnb[t] - bnm[t] * sc;
    }

    int wm = wid & 1;
    int wn = wid >> 1;
    const uint4* Abase = g_afrag + ((size_t)b * NCHUNK * 400 + (p0 >> 4) + wm * 2) * 128 + lid;
    const uint4* Bbase = g_wfrag + wn * 512 + lid;

    float acc[2][8][4];
#pragma unroll
    for (int mt = 0; mt < 2; mt++)
#pragma unroll
        for (int nt = 0; nt < 8; nt++)
#pragma unroll
            for (int j = 0; j < 4; j++) acc[mt][nt][j] = 0.f;

    uint4 af[2][2], bf[2][4];
    LOADSTEP(0, 0);
#pragma unroll 1
    for (int sp = 0; sp < 20; sp++) {
        int s1 = 2 * sp + 1;
        LOADSTEP(s1, 1);
        MMASTEP(0);
        if (s1 < 39) LOADSTEP(s1 + 1, 0);
        MMASTEP(1);
    }

    __syncthreads();

    // ---- epilogue: BN + SiLU via SMEM transpose ----
    const float* scs = (const float*)(smem + SM_BN);
    const float* shs = scs + 256;
    float* sO = (float*)(smem + SM_ST);
#pragma unroll
    for (int half = 0; half < 2; half++) {
        if ((wn >> 1) == half) {
#pragma unroll
            for (int mt = 0; mt < 2; mt++)
#pragma unroll
                for (int nt = 0; nt < 8; nt++)
#pragma unroll
                    for (int j = 0; j < 4; j++) {
                        int row = wm * 32 + mt * 16 + (lid >> 2) + 8 * (j >> 1);
                        int col = (wn & 1) * 64 + nt * 8 + 2 * (lid & 3) + (j & 1);
                        sO[col * OPITCH + row] = acc[mt][nt][j];
                    }
        }
        __syncthreads();
#pragma unroll
        for (int it = 0; it < 32; it++) {
            int idx = it * 256 + t;
            int c2l = idx >> 6, pp = idx & 63;
            int c2 = half * 128 + c2l;
            float v = sO[c2l * OPITCH + pp] * scs[c2] + shs[c2];
            out[((size_t)b * C2 + c2) * P_ + p0 + pp] = v / (1.f + __expf(-v));
        }
        __syncthreads();
    }
}

// ---------------------------------------------------------------------------
extern "C" void kernel_launch(void* const* d_in, const int* in_sizes, int n_in,
                              void* d_out, int out_size) {
    const float* x   = (const float*)d_in[0];
    const float* pw  = (const float*)d_in[1];
    const float* pb  = (const float*)d_in[2];
    const float* cw  = (const float*)d_in[3];
    const float* bng = (const float*)d_in[4];
    const float* bnb = (const float*)d_in[5];
    const float* bnm = (const float*)d_in[6];
    const float* bnv = (const float*)d_in[7];
    float* out = (float*)d_out;

    cudaFuncSetAttribute(offset_kernel, cudaFuncAttributeMaxDynamicSharedMemorySize, 55296);
    cudaFuncSetAttribute(gemm_kernel,   cudaFuncAttributeMaxDynamicSharedMemorySize, SM_TOTAL);

    prep_kernel<<<80, 256>>>(cw, pw);
    offset_kernel<<<B_ * P_ / 256, 256, 55296>>>(x, pb);
    dim3 gg(P_ / 256, NCHUNK, B_);
    gather_kernel<<<gg, 256>>>();
    dim3 g2(P_ / TPIX, B_);
    gemm_kernel<<<g2, 256, SM_TOTAL>>>(bng, bnb, bnm, bnv, out);
}